// round 9
// baseline (speedup 1.0000x reference)
#include <cuda_runtime.h>
#include <math.h>

#define BATCH   128
#define NT      512
#define NC      512
#define EMB     256
#define DK      60
#define DV      60
#define NTOK    (BATCH * NT)
#define NCTOK   (BATCH * NC)

typedef unsigned long long u64;

__device__ __forceinline__ u64 pack2(float x) {
    u64 r; asm("mov.b64 %0, {%1, %1};" : "=l"(r) : "f"(x)); return r;
}
__device__ __forceinline__ void ffma2(u64& d, u64 a, u64 b) {
    asm("fma.rn.f32x2 %0, %1, %2, %3;" : "=l"(d) : "l"(a), "l"(b), "l"(d));
}
__device__ __forceinline__ u64 mul2(u64 a, u64 b) {
    u64 r; asm("mul.rn.f32x2 %0, %1, %2;" : "=l"(r) : "l"(a), "l"(b)); return r;
}
__device__ __forceinline__ float2 unpack2(u64 v) {
    float2 f; asm("mov.b64 {%0, %1}, %2;" : "=f"(f.x), "=f"(f.y) : "l"(v)); return f;
}

__device__ float g_q [NTOK  * DK];
__device__ float g_k [NCTOK * DK];
__device__ float g_v [NCTOK * DV];
__device__ float g_rq[NTOK];           // 1/|q|
__device__ float g_rk[NCTOK];          // 1/|k|

// ---------------------------------------------------------------------------
// proj_q: 256 tokens/block, 256 threads, 8t x 8j tiles, k-chunked (FFMA2)
// ---------------------------------------------------------------------------
__global__ void __launch_bounds__(256) proj_q_kernel(
    const int* __restrict__ items, const float* __restrict__ tvec,
    const float* __restrict__ W, const float* __restrict__ bias)
{
    extern __shared__ float sm[];
    int*   its  = (int*)sm;
    float* Wt   = sm + 256;            // [64][64]  swizzled
    float* embT = Wt + 64 * 64;        // [64][264] swizzled

    const int tid = threadIdx.x;
    const int tx  = tid & 7;
    const int ty  = tid >> 3;
    const int base = blockIdx.x * 256;

    its[tid] = items[base + tid];

    u64 acc[8][4];
#pragma unroll
    for (int i = 0; i < 8; i++)
#pragma unroll
        for (int j = 0; j < 4; j++) acc[i][j] = 0ull;

    for (int c0 = 0; c0 < 4; c0++) {
        __syncthreads();
        for (int idx = tid; idx < 64 * 16; idx += 256) {
            int j = idx >> 4, l = idx & 15;
            float4 w = make_float4(0.f, 0.f, 0.f, 0.f);
            if (j < DK) w = *(const float4*)(W + j * EMB + c0 * 64 + l * 4);
            int js = j ^ ((l & 7) << 2);
            Wt[(4 * l + 0) * 64 + js] = w.x;
            Wt[(4 * l + 1) * 64 + js] = w.y;
            Wt[(4 * l + 2) * 64 + js] = w.z;
            Wt[(4 * l + 3) * 64 + js] = w.w;
        }
        for (int idx = tid; idx < 256 * 16; idx += 256) {
            int t = idx >> 4, l = idx & 15;
            float4 e = *(const float4*)(tvec + (size_t)its[t] * EMB + c0 * 64 + l * 4);
            int ts = t ^ ((l & 7) << 2);
            embT[(4 * l + 0) * 264 + ts] = e.x;
            embT[(4 * l + 1) * 264 + ts] = e.y;
            embT[(4 * l + 2) * 264 + ts] = e.z;
            embT[(4 * l + 3) * 264 + ts] = e.w;
        }
        __syncthreads();

#pragma unroll 4
        for (int kc = 0; kc < 64; kc++) {
            int sw = ((kc >> 2) & 7) << 2;
            float4 a0 = *(const float4*)(embT + kc * 264 + ((ty * 8) ^ sw));
            float4 a1 = *(const float4*)(embT + kc * 264 + ((ty * 8 + 4) ^ sw));
            ulonglong2 b0 = *(const ulonglong2*)(Wt + kc * 64 + ((tx * 8) ^ sw));
            ulonglong2 b1 = *(const ulonglong2*)(Wt + kc * 64 + ((tx * 8 + 4) ^ sw));
            float av[8] = {a0.x, a0.y, a0.z, a0.w, a1.x, a1.y, a1.z, a1.w};
#pragma unroll
            for (int i = 0; i < 8; i++) {
                u64 a = pack2(av[i]);
                ffma2(acc[i][0], a, b0.x);
                ffma2(acc[i][1], a, b0.y);
                ffma2(acc[i][2], a, b1.x);
                ffma2(acc[i][3], a, b1.y);
            }
        }
    }

    float bj[8];
#pragma unroll
    for (int j = 0; j < 8; j++) {
        int jj = tx * 8 + j;
        bj[j] = (jj < DK) ? bias[jj] : 0.f;
    }

#pragma unroll
    for (int i = 0; i < 8; i++) {
        int tok = base + ty * 8 + i;
        float v[8];
        float2 p;
        p = unpack2(acc[i][0]); v[0] = p.x + bj[0]; v[1] = p.y + bj[1];
        p = unpack2(acc[i][1]); v[2] = p.x + bj[2]; v[3] = p.y + bj[3];
        p = unpack2(acc[i][2]); v[4] = p.x + bj[4]; v[5] = p.y + bj[5];
        p = unpack2(acc[i][3]); v[6] = p.x + bj[6]; v[7] = p.y + bj[7];
        if (tx < 7) {
            *(float4*)(g_q + (size_t)tok * DK + tx * 8)     = make_float4(v[0], v[1], v[2], v[3]);
            *(float4*)(g_q + (size_t)tok * DK + tx * 8 + 4) = make_float4(v[4], v[5], v[6], v[7]);
        } else {
            *(float4*)(g_q + (size_t)tok * DK + 56) = make_float4(v[0], v[1], v[2], v[3]);
        }
        float sq = v[0]*v[0] + v[1]*v[1] + v[2]*v[2] + v[3]*v[3];
        if (tx < 7) sq += v[4]*v[4] + v[5]*v[5] + v[6]*v[6] + v[7]*v[7];
#pragma unroll
        for (int o = 4; o; o >>= 1) sq += __shfl_xor_sync(0xffffffffu, sq, o);
        if (tx == 0) g_rq[tok] = rsqrtf(sq);
    }
}

// ---------------------------------------------------------------------------
// proj_kv: 128 tokens/block, 256 threads, 8t x 8j over 128 j (k | pad | v)
// ---------------------------------------------------------------------------
__global__ void __launch_bounds__(256) proj_kv_kernel(
    const int* __restrict__ items, const float* __restrict__ cvec,
    const float* __restrict__ Wk, const float* __restrict__ bk,
    const float* __restrict__ Wv, const float* __restrict__ bv)
{
    extern __shared__ float sm[];
    int*   its  = (int*)sm;
    float* Wt   = sm + 128;            // [64][128] swizzled
    float* embT = Wt + 64 * 128;       // [64][136] swizzled

    const int tid = threadIdx.x;
    const int tx  = tid & 15;
    const int ty  = tid >> 4;
    const int base = blockIdx.x * 128;

    if (tid < 128) its[tid] = items[base + tid];

    u64 acc[8][4];
#pragma unroll
    for (int i = 0; i < 8; i++)
#pragma unroll
        for (int j = 0; j < 4; j++) acc[i][j] = 0ull;

    for (int c0 = 0; c0 < 4; c0++) {
        __syncthreads();
        for (int idx = tid; idx < 128 * 16; idx += 256) {
            int j = idx >> 4, l = idx & 15;
            float4 w = make_float4(0.f, 0.f, 0.f, 0.f);
            if (j < DK)                      w = *(const float4*)(Wk + j * EMB + c0 * 64 + l * 4);
            else if (j >= 64 && j < 64 + DV) w = *(const float4*)(Wv + (j - 64) * EMB + c0 * 64 + l * 4);
            int js = j ^ ((l & 7) << 2);
            Wt[(4 * l + 0) * 128 + js] = w.x;
            Wt[(4 * l + 1) * 128 + js] = w.y;
            Wt[(4 * l + 2) * 128 + js] = w.z;
            Wt[(4 * l + 3) * 128 + js] = w.w;
        }
        for (int idx = tid; idx < 128 * 16; idx += 256) {
            int t = idx >> 4, l = idx & 15;
            float4 e = *(const float4*)(cvec + (size_t)its[t] * EMB + c0 * 64 + l * 4);
            int ts = t ^ ((l & 7) << 2);
            embT[(4 * l + 0) * 136 + ts] = e.x;
            embT[(4 * l + 1) * 136 + ts] = e.y;
            embT[(4 * l + 2) * 136 + ts] = e.z;
            embT[(4 * l + 3) * 136 + ts] = e.w;
        }
        __syncthreads();

#pragma unroll 4
        for (int kc = 0; kc < 64; kc++) {
            int sw = ((kc >> 2) & 7) << 2;
            float4 a0 = *(const float4*)(embT + kc * 136 + ((ty * 8) ^ sw));
            float4 a1 = *(const float4*)(embT + kc * 136 + ((ty * 8 + 4) ^ sw));
            ulonglong2 b0 = *(const ulonglong2*)(Wt + kc * 128 + ((tx * 8) ^ sw));
            ulonglong2 b1 = *(const ulonglong2*)(Wt + kc * 128 + ((tx * 8 + 4) ^ sw));
            float av[8] = {a0.x, a0.y, a0.z, a0.w, a1.x, a1.y, a1.z, a1.w};
#pragma unroll
            for (int i = 0; i < 8; i++) {
                u64 a = pack2(av[i]);
                ffma2(acc[i][0], a, b0.x);
                ffma2(acc[i][1], a, b0.y);
                ffma2(acc[i][2], a, b1.x);
                ffma2(acc[i][3], a, b1.y);
            }
        }
    }

    float bj[8];
#pragma unroll
    for (int j = 0; j < 8; j++) {
        int jj = tx * 8 + j;
        float bb = 0.f;
        if (jj < DK) bb = bk[jj];
        else if (jj >= 64 && jj < 64 + DV) bb = bv[jj - 64];
        bj[j] = bb;
    }

#pragma unroll
    for (int i = 0; i < 8; i++) {
        int tok = base + ty * 8 + i;
        float v[8];
        float2 p;
        p = unpack2(acc[i][0]); v[0] = p.x + bj[0]; v[1] = p.y + bj[1];
        p = unpack2(acc[i][1]); v[2] = p.x + bj[2]; v[3] = p.y + bj[3];
        p = unpack2(acc[i][2]); v[4] = p.x + bj[4]; v[5] = p.y + bj[5];
        p = unpack2(acc[i][3]); v[6] = p.x + bj[6]; v[7] = p.y + bj[7];
        if (tx < 7) {
            *(float4*)(g_k + (size_t)tok * DK + tx * 8)     = make_float4(v[0], v[1], v[2], v[3]);
            *(float4*)(g_k + (size_t)tok * DK + tx * 8 + 4) = make_float4(v[4], v[5], v[6], v[7]);
        } else if (tx == 7) {
            *(float4*)(g_k + (size_t)tok * DK + 56) = make_float4(v[0], v[1], v[2], v[3]);
        } else if (tx < 15) {
            *(float4*)(g_v + (size_t)tok * DV + tx * 8 - 64)     = make_float4(v[0], v[1], v[2], v[3]);
            *(float4*)(g_v + (size_t)tok * DV + tx * 8 - 64 + 4) = make_float4(v[4], v[5], v[6], v[7]);
        } else {
            *(float4*)(g_v + (size_t)tok * DV + 56) = make_float4(v[0], v[1], v[2], v[3]);
        }
        float sq = 0.f;
        if (tx < 7)  sq = v[0]*v[0]+v[1]*v[1]+v[2]*v[2]+v[3]*v[3]+v[4]*v[4]+v[5]*v[5]+v[6]*v[6]+v[7]*v[7];
        if (tx == 7) sq = v[0]*v[0]+v[1]*v[1]+v[2]*v[2]+v[3]*v[3];
#pragma unroll
        for (int o = 4; o; o >>= 1) sq += __shfl_xor_sync(0xffffffffu, sq, o);
        if (tx == 0) g_rk[tok] = rsqrtf(sq);
    }
}

// ---------------------------------------------------------------------------
// attn (+ fused output projection): 128q x 512ctx, 256 threads, 4r x 8c tiles.
// Epilogue reuses smem: Rt over Qt/KtT/Vs, AOt over Pt. smem 100.6KB, 2 CTA/SM.
// ---------------------------------------------------------------------------
#define QT_W 136
#define KT_W 72
#define PT_W 132
#define RT_W 264

__global__ void __launch_bounds__(256) attn_kernel(
    const float* __restrict__ pos_bias,
    const float* __restrict__ R_w, const float* __restrict__ R_b,
    float* __restrict__ out)
{
    extern __shared__ float sm[];
    float*  Qt   = sm;                        // [60][136] swizzled, Qt[k][r]
    float*  KtT  = Qt + 60 * QT_W;            // [60][72]  swizzled, KtT[k][c]
    float*  Vs   = KtT + 60 * KT_W;           // [64][64]  row-major V[c][dv]
    float*  Pt   = Vs + 64 * 64;              // [64][132] swizzled, Pt[c][r]
    float2* rkpb = (float2*)(Pt + 64 * PT_W); // [64]
    float*  Rt   = sm;                        // [60][264] epilogue reuse (<= Qt+KtT+Vs)
    float*  AOt  = Pt;                        // [60][132] epilogue reuse

    const int b   = blockIdx.y;
    const int tq0 = blockIdx.x * 128;
    const int tid = threadIdx.x;
    const int tx  = tid & 7;                  // c0 = dv0 = tx*8
    const int ty  = tid >> 3;                 // 0..31, r0 = ty*4
    const int r0  = ty * 4, c0 = tx * 8;

    // stage Qt (transposed, swizzled)
    for (int idx = tid; idx < 128 * 16; idx += 256) {
        int t = idx >> 4, l = idx & 15;
        if (l < 15) {
            float4 q = *(const float4*)(g_q + (size_t)(b * NT + tq0 + t) * DK + l * 4);
            int ts = t ^ ((l & 7) << 2);
            Qt[(4 * l + 0) * QT_W + ts] = q.x;
            Qt[(4 * l + 1) * QT_W + ts] = q.y;
            Qt[(4 * l + 2) * QT_W + ts] = q.z;
            Qt[(4 * l + 3) * QT_W + ts] = q.w;
        }
    }

    float rq_r[4];
#pragma unroll
    for (int i = 0; i < 4; i++) rq_r[i] = g_rq[b * NT + tq0 + r0 + i];

    float m[4], lsum[4];
#pragma unroll
    for (int i = 0; i < 4; i++) { m[i] = -1e30f; lsum[i] = 0.f; }
    u64 oa[4][4];
#pragma unroll
    for (int i = 0; i < 4; i++)
#pragma unroll
        for (int j = 0; j < 4; j++) oa[i][j] = 0ull;

    for (int ct = 0; ct < 8; ct++) {
        const int cb = ct * 64;
        __syncthreads();
        for (int idx = tid; idx < 64 * 16; idx += 256) {
            int c = idx >> 4, l = idx & 15;
            if (l < 15) {
                float4 k4 = *(const float4*)(g_k + (size_t)(b * NC + cb + c) * DK + l * 4);
                int cs = c ^ ((l & 7) << 2);
                KtT[(4 * l + 0) * KT_W + cs] = k4.x;
                KtT[(4 * l + 1) * KT_W + cs] = k4.y;
                KtT[(4 * l + 2) * KT_W + cs] = k4.z;
                KtT[(4 * l + 3) * KT_W + cs] = k4.w;
            }
        }
        for (int idx = tid; idx < 64 * 16; idx += 256) {
            int c = idx >> 4, l = idx & 15;
            if (l < 15)
                *(float4*)(Vs + c * 64 + l * 4) =
                    *(const float4*)(g_v + (size_t)(b * NC + cb + c) * DV + l * 4);
            else
                *(float4*)(Vs + c * 64 + 60) = make_float4(0.f, 0.f, 0.f, 0.f);
        }
        if (tid < 64) rkpb[tid] = make_float2(g_rk[b * NC + cb + tid], pos_bias[cb + tid]);
        __syncthreads();

        // ---- scores: 4r x 8c per thread (FFMA2) ----
        u64 s2[4][4];
#pragma unroll
        for (int i = 0; i < 4; i++)
#pragma unroll
            for (int j = 0; j < 4; j++) s2[i][j] = 0ull;

#pragma unroll 4
        for (int k = 0; k < 60; k++) {
            int key = ((k >> 2) & 7) << 2;
            float4 a0 = *(const float4*)(Qt + k * QT_W + (r0 ^ key));
            ulonglong2 b0 = *(const ulonglong2*)(KtT + k * KT_W + (c0 ^ key));
            ulonglong2 b1 = *(const ulonglong2*)(KtT + k * KT_W + ((c0 + 4) ^ key));
            float av[4] = {a0.x, a0.y, a0.z, a0.w};
#pragma unroll
            for (int i = 0; i < 4; i++) {
                u64 a = pack2(av[i]);
                ffma2(s2[i][0], a, b0.x);
                ffma2(s2[i][1], a, b0.y);
                ffma2(s2[i][2], a, b1.x);
                ffma2(s2[i][3], a, b1.y);
            }
        }

        float s[4][8];
#pragma unroll
        for (int i = 0; i < 4; i++) {
#pragma unroll
            for (int j = 0; j < 4; j++) {
                float2 p = unpack2(s2[i][j]);
                s[i][2 * j] = p.x; s[i][2 * j + 1] = p.y;
            }
        }

        float kf[8], pb[8];
#pragma unroll
        for (int j = 0; j < 8; j++) {
            float2 f2 = rkpb[c0 + j];
            kf[j] = f2.x; pb[j] = f2.y;
        }

        // ---- cosine scale + bias + online softmax (stats in registers) ----
#pragma unroll
        for (int i = 0; i < 4; i++) {
            float rm = -1e30f;
#pragma unroll
            for (int j = 0; j < 8; j++) {
                s[i][j] = s[i][j] * fminf(rq_r[i] * kf[j], 1e6f) + pb[j];
                rm = fmaxf(rm, s[i][j]);
            }
            rm = fmaxf(rm, __shfl_xor_sync(0xffffffffu, rm, 1));
            rm = fmaxf(rm, __shfl_xor_sync(0xffffffffu, rm, 2));
            rm = fmaxf(rm, __shfl_xor_sync(0xffffffffu, rm, 4));
            float newm = fmaxf(m[i], rm);
            float corr = __expf(m[i] - newm);
            m[i] = newm;
            float sum = 0.f;
#pragma unroll
            for (int j = 0; j < 8; j++) {
                s[i][j] = __expf(s[i][j] - newm);
                sum += s[i][j];
            }
            sum += __shfl_xor_sync(0xffffffffu, sum, 1);
            sum += __shfl_xor_sync(0xffffffffu, sum, 2);
            sum += __shfl_xor_sync(0xffffffffu, sum, 4);
            lsum[i] = lsum[i] * corr + sum;
            u64 c2 = pack2(corr);
#pragma unroll
            for (int j = 0; j < 4; j++) oa[i][j] = mul2(oa[i][j], c2);
        }

        // ---- write P transposed (warp-local rows) ----
#pragma unroll
        for (int j = 0; j < 8; j++) {
            int c = c0 + j;
            int key = ((c ^ (c >> 3)) & 7) << 2;
            *(float4*)(Pt + c * PT_W + (r0 ^ key)) =
                make_float4(s[0][j], s[1][j], s[2][j], s[3][j]);
        }
        __syncwarp();

        // ---- PV: 4r x 8dv per thread over 64 c (FFMA2) ----
#pragma unroll 4
        for (int c = 0; c < 64; c++) {
            int key = ((c ^ (c >> 3)) & 7) << 2;
            float4 p0 = *(const float4*)(Pt + c * PT_W + (r0 ^ key));
            ulonglong2 v0 = *(const ulonglong2*)(Vs + c * 64 + c0);
            ulonglong2 v1 = *(const ulonglong2*)(Vs + c * 64 + c0 + 4);
            float pv[4] = {p0.x, p0.y, p0.z, p0.w};
#pragma unroll
            for (int i = 0; i < 4; i++) {
                u64 a = pack2(pv[i]);
                ffma2(oa[i][0], a, v0.x);
                ffma2(oa[i][1], a, v0.y);
                ffma2(oa[i][2], a, v1.x);
                ffma2(oa[i][3], a, v1.y);
            }
        }
    }

    // ================= fused output projection =================
    __syncthreads();   // everyone done with Qt/KtT/Vs/Pt attention reads

    // normalized AO, transposed into AOt[d][r] (over Pt storage)
    {
        float aov[4][8];
#pragma unroll
        for (int i = 0; i < 4; i++) {
            float il = __fdividef(1.f, lsum[i]);
            float2 p;
            p = unpack2(oa[i][0]); aov[i][0] = p.x * il; aov[i][1] = p.y * il;
            p = unpack2(oa[i][1]); aov[i][2] = p.x * il; aov[i][3] = p.y * il;
            p = unpack2(oa[i][2]); aov[i][4] = p.x * il; aov[i][5] = p.y * il;
            p = unpack2(oa[i][3]); aov[i][6] = p.x * il; aov[i][7] = p.y * il;
        }
#pragma unroll
        for (int j = 0; j < 8; j++) {
            int d = c0 + j;                       // d in [0,64); rows 60..63 unused
            int key = ((d >> 2) & 7) << 2;
            *(float4*)(AOt + d * PT_W + (r0 ^ key)) =
                make_float4(aov[0][j], aov[1][j], aov[2][j], aov[3][j]);
        }
    }
    // stage Rt[d][e] = R_w[e][d]  (conflict-free STS: e consecutive per warp)
    for (int idx = tid; idx < 256 * 16; idx += 256) {
        int e = idx & 255, l = idx >> 8;          // this pass: l fixed 0..15 slice? no:
        (void)e; (void)l;
        break;
    }
    for (int idx = tid; idx < 16 * 256; idx += 256) {
        int l = idx >> 8;                         // 0..15
        int e = idx & 255;
        if (l < 15) {
            float4 w = *(const float4*)(R_w + (size_t)e * DV + l * 4);
            Rt[(4 * l + 0) * RT_W + e] = w.x;
            Rt[(4 * l + 1) * RT_W + e] = w.y;
            Rt[(4 * l + 2) * RT_W + e] = w.z;
            Rt[(4 * l + 3) * RT_W + e] = w.w;
        }
    }
    __syncthreads();

    // out[128][256] = AO[128][60] @ Rt (+R_b): 4 e-blocks of 64
#pragma unroll 1
    for (int eb = 0; eb < 4; eb++) {
        const int e0 = eb * 64 + tx * 8;
        u64 acc[4][4];
#pragma unroll
        for (int i = 0; i < 4; i++)
#pragma unroll
            for (int j = 0; j < 4; j++) acc[i][j] = 0ull;

#pragma unroll 4
        for (int k = 0; k < 60; k++) {
            int key = ((k >> 2) & 7) << 2;
            float4 a0 = *(const float4*)(AOt + k * PT_W + (r0 ^ key));
            ulonglong2 b0 = *(const ulonglong2*)(Rt + k * RT_W + e0);
            ulonglong2 b1 = *(const ulonglong2*)(Rt + k * RT_W + e0 + 4);
            float av[4] = {a0.x, a0.y, a0.z, a0.w};
#pragma unroll
            for (int i = 0; i < 4; i++) {
                u64 a = pack2(av[i]);
                ffma2(acc[i][0], a, b0.x);
                ffma2(acc[i][1], a, b0.y);
                ffma2(acc[i][2], a, b1.x);
                ffma2(acc[i][3], a, b1.y);
            }
        }

        float4 rb0 = *(const float4*)(R_b + e0);
        float4 rb1 = *(const float4*)(R_b + e0 + 4);
#pragma unroll
        for (int i = 0; i < 4; i++) {
            size_t o = (size_t)(b * NT + tq0 + r0 + i) * EMB + e0;
            float2 p0 = unpack2(acc[i][0]), p1 = unpack2(acc[i][1]);
            float2 p2 = unpack2(acc[i][2]), p3 = unpack2(acc[i][3]);
            *(float4*)(out + o)     = make_float4(p0.x + rb0.x, p0.y + rb0.y, p1.x + rb0.z, p1.y + rb0.w);
            *(float4*)(out + o + 4) = make_float4(p2.x + rb1.x, p2.y + rb1.y, p3.x + rb1.z, p3.y + rb1.w);
        }
    }
}

// ---------------------------------------------------------------------------
extern "C" void kernel_launch(void* const* d_in, const int* in_sizes, int n_in,
                              void* d_out, int out_size)
{
    const int*   titems   = (const int*)  d_in[0];
    const int*   citems   = (const int*)  d_in[1];
    const float* tvec     = (const float*)d_in[2];
    const float* cvec     = (const float*)d_in[3];
    const float* At_w     = (const float*)d_in[4];
    const float* At_b     = (const float*)d_in[5];
    const float* Ac_w     = (const float*)d_in[6];
    const float* Ac_b     = (const float*)d_in[7];
    const float* Bc_w     = (const float*)d_in[8];
    const float* Bc_b     = (const float*)d_in[9];
    const float* pos_bias = (const float*)d_in[10];
    const float* R_w      = (const float*)d_in[11];
    const float* R_b      = (const float*)d_in[12];
    float* out = (float*)d_out;

    const int smem_q   = (256 + 64 * 64 + 64 * 264) * 4;                          // 84992
    const int smem_kv  = (128 + 64 * 128 + 64 * 136) * 4;                         // 68096
    const int smem_at  = (60 * QT_W + 60 * KT_W + 64 * 64 + 64 * PT_W + 128) * 4; // 100608

    cudaFuncSetAttribute(proj_q_kernel,  cudaFuncAttributeMaxDynamicSharedMemorySize, smem_q);
    cudaFuncSetAttribute(proj_kv_kernel, cudaFuncAttributeMaxDynamicSharedMemorySize, smem_kv);
    cudaFuncSetAttribute(attn_kernel,    cudaFuncAttributeMaxDynamicSharedMemorySize, smem_at);

    proj_q_kernel  <<< NTOK / 256,  256, smem_q  >>>(titems, tvec, At_w, At_b);
    proj_kv_kernel <<< NCTOK / 128, 256, smem_kv >>>(citems, cvec, Ac_w, Ac_b, Bc_w, Bc_b);
    attn_kernel    <<< dim3(NT / 128, BATCH), 256, smem_at >>>(pos_bias, R_w, R_b, out);
}